// round 2
// baseline (speedup 1.0000x reference)
#include <cuda_runtime.h>

#define NN 50000
#define NE 800000
#define HID 64
#define NG 64

// ---------------- persistent device scratch (allocation-free) ----------------
__device__ __align__(16) float g_bufA[NN * HID];   // layer inputs (post-LN)
__device__ __align__(16) float g_bufB[NN * HID];   // hs = (x@W) * dinv
__device__ float g_dinv[NN];
__device__ int   g_deg[NN];
__device__ int   g_rowptr[NN + 1];
__device__ int   g_cursor[NN];
__device__ int   g_col[NE];
__device__ float g_pool[NG * HID];
__device__ int   g_cnt[NG];

// ---------------- setup kernels ----------------
__global__ __launch_bounds__(256) void k_zero() {
    int i = blockIdx.x * blockDim.x + threadIdx.x;
    if (i < NN) g_deg[i] = 0;
    if (i < NG * HID) g_pool[i] = 0.f;
    if (i < NG) g_cnt[i] = 0;
}

__global__ __launch_bounds__(256) void k_deg(const int* __restrict__ dst) {
    int e = blockIdx.x * blockDim.x + threadIdx.x;
    if (e < NE) atomicAdd(&g_deg[dst[e]], 1);
}

// single-block exclusive scan of in-degrees -> rowptr/cursor, plus dinv
__global__ __launch_bounds__(1024) void k_scan() {
    const int T = 1024;
    const int PER = (NN + T - 1) / T;  // 49
    __shared__ int sh[T];
    int t = threadIdx.x;
    int beg = t * PER;
    int end = min(beg + PER, NN);
    int s = 0;
    for (int i = beg; i < end; i++) s += g_deg[i];
    sh[t] = s;
    __syncthreads();
    for (int off = 1; off < T; off <<= 1) {
        int v = (t >= off) ? sh[t - off] : 0;
        __syncthreads();
        sh[t] += v;
        __syncthreads();
    }
    int run = (t == 0) ? 0 : sh[t - 1];
    for (int i = beg; i < end; i++) {
        g_rowptr[i] = run;
        g_cursor[i] = run;
        run += g_deg[i];
        g_dinv[i] = rsqrtf((float)(g_deg[i] + 1));
    }
    if (t == T - 1) g_rowptr[NN] = sh[T - 1];
}

__global__ __launch_bounds__(256) void k_fill(const int* __restrict__ src,
                                              const int* __restrict__ dst) {
    int e = blockIdx.x * blockDim.x + threadIdx.x;
    if (e < NE) {
        int d = dst[e];
        int p = atomicAdd(&g_cursor[d], 1);
        g_col[p] = src[e];
    }
}

// ---------------- dense kernels ----------------
// layer 1: hs = (emb[node] @ W1) * dinv   (EMB_DIM = 4)
__global__ __launch_bounds__(128) void k_mm1(const int* __restrict__ node,
                                             const float* __restrict__ emb,
                                             const float* __restrict__ W1) {
    __shared__ float sW[4 * HID];
    int t = threadIdx.x;
    if (t < 4 * HID) sW[t] = W1[t];
    if (t + 128 < 4 * HID) sW[t + 128] = W1[t + 128];
    __syncthreads();
    int n = blockIdx.x * 128 + t;
    if (n >= NN) return;
    float4 e = ((const float4*)emb)[node[n]];
    float di = g_dinv[n];
    float4* o = (float4*)(g_bufB + (size_t)n * HID);
#pragma unroll
    for (int j4 = 0; j4 < 16; j4++) {
        float r[4];
#pragma unroll
        for (int u = 0; u < 4; u++) {
            int j = 4 * j4 + u;
            r[u] = (e.x * sW[j] + e.y * sW[64 + j] + e.z * sW[128 + j] + e.w * sW[192 + j]) * di;
        }
        o[j4] = make_float4(r[0], r[1], r[2], r[3]);
    }
}

// layers 2/3: hs = (bufA @ W) * dinv
__global__ __launch_bounds__(128) void k_mm(const float* __restrict__ W) {
    __shared__ float sW[HID * HID];
    int t = threadIdx.x;
    for (int i = t; i < HID * HID; i += 128) sW[i] = W[i];
    __syncthreads();
    int n = blockIdx.x * 128 + t;
    if (n >= NN) return;
    float acc[HID];
#pragma unroll
    for (int j = 0; j < HID; j++) acc[j] = 0.f;
    const float4* x4 = (const float4*)(g_bufA + (size_t)n * HID);
    for (int k4 = 0; k4 < 16; k4++) {
        float4 xv = x4[k4];
        const float4* w0 = (const float4*)(sW + (4 * k4 + 0) * HID);
        const float4* w1 = (const float4*)(sW + (4 * k4 + 1) * HID);
        const float4* w2 = (const float4*)(sW + (4 * k4 + 2) * HID);
        const float4* w3 = (const float4*)(sW + (4 * k4 + 3) * HID);
#pragma unroll
        for (int j = 0; j < 16; j++) {
            float4 a = w0[j], b = w1[j], c = w2[j], d = w3[j];
            acc[4 * j + 0] = fmaf(xv.x, a.x, fmaf(xv.y, b.x, fmaf(xv.z, c.x, fmaf(xv.w, d.x, acc[4 * j + 0]))));
            acc[4 * j + 1] = fmaf(xv.x, a.y, fmaf(xv.y, b.y, fmaf(xv.z, c.y, fmaf(xv.w, d.y, acc[4 * j + 1]))));
            acc[4 * j + 2] = fmaf(xv.x, a.z, fmaf(xv.y, b.z, fmaf(xv.z, c.z, fmaf(xv.w, d.z, acc[4 * j + 2]))));
            acc[4 * j + 3] = fmaf(xv.x, a.w, fmaf(xv.y, b.w, fmaf(xv.z, c.w, fmaf(xv.w, d.w, acc[4 * j + 3]))));
        }
    }
    float di = g_dinv[n];
    float4* o = (float4*)(g_bufB + (size_t)n * HID);
#pragma unroll
    for (int j = 0; j < 16; j++)
        o[j] = make_float4(acc[4 * j] * di, acc[4 * j + 1] * di, acc[4 * j + 2] * di, acc[4 * j + 3] * di);
}

// ---------------- fused gather + relu (+LN | +pool) ----------------
// warp per node, float2 per lane (64 features)
template <bool LN, bool POOL>
__global__ __launch_bounds__(256) void k_gather(const float* __restrict__ bias,
                                                const float* __restrict__ lng,
                                                const float* __restrict__ lnb,
                                                const int* __restrict__ batch) {
    int n = (blockIdx.x * blockDim.x + threadIdx.x) >> 5;
    int lane = threadIdx.x & 31;
    if (n >= NN) return;
    const float2* hs2 = (const float2*)g_bufB;
    float2 acc = __ldg(&hs2[(size_t)n * 32 + lane]);  // self-loop term (pre-scaled)
    int beg = g_rowptr[n], end = g_rowptr[n + 1];
    int e = beg;
    for (; e + 4 <= end; e += 4) {
        int s0 = g_col[e], s1 = g_col[e + 1], s2 = g_col[e + 2], s3 = g_col[e + 3];
        float2 v0 = __ldg(&hs2[(size_t)s0 * 32 + lane]);
        float2 v1 = __ldg(&hs2[(size_t)s1 * 32 + lane]);
        float2 v2 = __ldg(&hs2[(size_t)s2 * 32 + lane]);
        float2 v3 = __ldg(&hs2[(size_t)s3 * 32 + lane]);
        acc.x += (v0.x + v1.x) + (v2.x + v3.x);
        acc.y += (v0.y + v1.y) + (v2.y + v3.y);
    }
    for (; e < end; e++) {
        int s = g_col[e];
        float2 v = __ldg(&hs2[(size_t)s * 32 + lane]);
        acc.x += v.x;
        acc.y += v.y;
    }
    float di = g_dinv[n];
    int f = lane * 2;
    float vx = fmaxf(fmaf(di, acc.x, bias[f]), 0.f);
    float vy = fmaxf(fmaf(di, acc.y, bias[f + 1]), 0.f);
    if (LN) {
        float s = vx + vy;
#pragma unroll
        for (int o = 16; o; o >>= 1) s += __shfl_xor_sync(0xffffffffu, s, o);
        float mu = s * (1.f / 64.f);
        float dx = vx - mu, dy = vy - mu;
        float q = dx * dx + dy * dy;
#pragma unroll
        for (int o = 16; o; o >>= 1) q += __shfl_xor_sync(0xffffffffu, q, o);
        float r = rsqrtf(q * (1.f / 64.f) + 1e-5f);
        vx = fmaf(dx * r, lng[f], lnb[f]);
        vy = fmaf(dy * r, lng[f + 1], lnb[f + 1]);
    }
    if (POOL) {
        int g = batch[n];
        atomicAdd(&g_pool[g * HID + f], vx);
        atomicAdd(&g_pool[g * HID + f + 1], vy);
        if (lane == 0) atomicAdd(&g_cnt[g], 1);
    } else {
        ((float2*)g_bufA)[(size_t)n * 32 + lane] = make_float2(vx, vy);
    }
}

// ---------------- final MLP: out = (pool/cnt) @ pW1 + pb1, then @ pW2 + pb2 ----------------
__global__ __launch_bounds__(1024) void k_mlp(const float* __restrict__ pW1,
                                              const float* __restrict__ pb1,
                                              const float* __restrict__ pW2,
                                              const float* __restrict__ pb2,
                                              float* __restrict__ out) {
    __shared__ float sp[NG * HID];
    __shared__ float sh[NG * HID];
    int t = threadIdx.x;  // 1024
    for (int i = t; i < NG * HID; i += 1024) {
        int g = i >> 6;
        float c = (float)max(g_cnt[g], 1);
        sp[i] = g_pool[i] / c;
    }
    __syncthreads();
    for (int i = t; i < NG * HID; i += 1024) {
        int g = i >> 6, j = i & 63;
        float a = pb1[j];
        for (int k = 0; k < HID; k++) a = fmaf(sp[g * HID + k], pW1[k * HID + j], a);
        sh[i] = a;
    }
    __syncthreads();
    for (int i = t; i < NG * HID; i += 1024) {
        int g = i >> 6, j = i & 63;
        float a = pb2[j];
        for (int k = 0; k < HID; k++) a = fmaf(sh[g * HID + k], pW2[k * HID + j], a);
        out[i] = a;
    }
}

// ---------------- launcher ----------------
extern "C" void kernel_launch(void* const* d_in, const int* in_sizes, int n_in,
                              void* d_out, int out_size) {
    const int* node = (const int*)d_in[0];
    const int* src = (const int*)d_in[1];
    const int* dst = (const int*)d_in[2];
    const int* batch = (const int*)d_in[3];
    const float* emb = (const float*)d_in[4];
    const float* W1 = (const float*)d_in[5];
    const float* b1 = (const float*)d_in[6];
    const float* W2 = (const float*)d_in[7];
    const float* b2 = (const float*)d_in[8];
    const float* W3 = (const float*)d_in[9];
    const float* b3 = (const float*)d_in[10];
    const float* ln1g = (const float*)d_in[11];
    const float* ln1b = (const float*)d_in[12];
    const float* ln2g = (const float*)d_in[13];
    const float* ln2b = (const float*)d_in[14];
    const float* pW1 = (const float*)d_in[15];
    const float* pb1 = (const float*)d_in[16];
    const float* pW2 = (const float*)d_in[17];
    const float* pb2 = (const float*)d_in[18];
    float* out = (float*)d_out;

    const int TB = 256;
    k_zero<<<(NN + TB - 1) / TB, TB>>>();
    k_deg<<<(NE + TB - 1) / TB, TB>>>(dst);
    k_scan<<<1, 1024>>>();
    k_fill<<<(NE + TB - 1) / TB, TB>>>(src, dst);

    dim3 gmm((NN + 127) / 128);
    dim3 ggt((NN * 32 + TB - 1) / TB);

    // layer 1
    k_mm1<<<gmm, 128>>>(node, emb, W1);
    k_gather<true, false><<<ggt, TB>>>(b1, ln1g, ln1b, nullptr);
    // layer 2
    k_mm<<<gmm, 128>>>(W2);
    k_gather<true, false><<<ggt, TB>>>(b2, ln2g, ln2b, nullptr);
    // layer 3 (+ fused mean-pool accumulate)
    k_mm<<<gmm, 128>>>(W3);
    k_gather<false, true><<<ggt, TB>>>(b3, nullptr, nullptr, batch);
    // MLP head
    k_mlp<<<1, 1024>>>(pW1, pb1, pW2, pb2, out);
}

// round 3
// speedup vs baseline: 1.6078x; 1.6078x over previous
#include <cuda_runtime.h>

#define NN 50000
#define NE 800000
#define HID 64
#define NG 64
#define NB 196   // ceil(NN/256)

// ---------------- persistent device scratch (allocation-free) ----------------
__device__ __align__(16) float g_bufA[NN * HID];   // layer inputs (post-LN)
__device__ __align__(16) float g_bufB[NN * HID];   // hs = (x@W) * dinv
__device__ __align__(16) float g_e4s[NN * 4];      // emb[node]*dinv
__device__ float g_dinv[NN];
__device__ int   g_deg[NN];
__device__ int   g_rowptr[NN + 1];
__device__ int   g_cursor[NN];
__device__ int   g_col[NE];
__device__ int   g_bsum[NB];
__device__ int   g_boff[NB];
__device__ float g_pool[NG * HID];
__device__ int   g_cnt[NG];

// ---------------- setup kernels ----------------
__global__ __launch_bounds__(256) void k_zero() {
    int i = blockIdx.x * blockDim.x + threadIdx.x;
    if (i < NN) g_deg[i] = 0;
    if (i < NG * HID) g_pool[i] = 0.f;
    if (i < NG) g_cnt[i] = 0;
}

__global__ __launch_bounds__(256) void k_deg(const int* __restrict__ dst) {
    int e = blockIdx.x * blockDim.x + threadIdx.x;
    if (e < NE) atomicAdd(&g_deg[dst[e]], 1);
}

// scan phase A: per-block sums of degrees (coalesced)
__global__ __launch_bounds__(256) void k_scanA() {
    __shared__ int sh[256];
    int t = threadIdx.x;
    int i = blockIdx.x * 256 + t;
    sh[t] = (i < NN) ? g_deg[i] : 0;
    __syncthreads();
    for (int o = 128; o; o >>= 1) {
        if (t < o) sh[t] += sh[t + o];
        __syncthreads();
    }
    if (t == 0) g_bsum[blockIdx.x] = sh[0];
}

// scan phase B: exclusive scan of NB block sums (single small block)
__global__ __launch_bounds__(256) void k_scanB() {
    __shared__ int sh[256];
    int t = threadIdx.x;
    sh[t] = (t < NB) ? g_bsum[t] : 0;
    __syncthreads();
    for (int o = 1; o < 256; o <<= 1) {
        int v = (t >= o) ? sh[t - o] : 0;
        __syncthreads();
        sh[t] += v;
        __syncthreads();
    }
    if (t < NB) g_boff[t] = (t == 0) ? 0 : sh[t - 1];
    if (t == NB - 1) g_rowptr[NN] = sh[t];
}

// scan phase C: in-tile exclusive scan -> rowptr/cursor, plus dinv and e4s prep
__global__ __launch_bounds__(256) void k_scanC(const int* __restrict__ node,
                                               const float* __restrict__ emb) {
    __shared__ int sh[256];
    int t = threadIdx.x;
    int i = blockIdx.x * 256 + t;
    int d = (i < NN) ? g_deg[i] : 0;
    sh[t] = d;
    __syncthreads();
    for (int o = 1; o < 256; o <<= 1) {
        int v = (t >= o) ? sh[t - o] : 0;
        __syncthreads();
        sh[t] += v;
        __syncthreads();
    }
    if (i < NN) {
        int excl = g_boff[blockIdx.x] + sh[t] - d;
        g_rowptr[i] = excl;
        g_cursor[i] = excl;
        float di = rsqrtf((float)(d + 1));
        g_dinv[i] = di;
        float4 e = ((const float4*)emb)[node[i]];
        ((float4*)g_e4s)[i] = make_float4(e.x * di, e.y * di, e.z * di, e.w * di);
    }
}

__global__ __launch_bounds__(256) void k_fill(const int* __restrict__ src,
                                              const int* __restrict__ dst) {
    int e = blockIdx.x * blockDim.x + threadIdx.x;
    if (e < NE) {
        int d = dst[e];
        int p = atomicAdd(&g_cursor[d], 1);
        g_col[p] = src[e];
    }
}

// ---------------- layer 1 fully fused: 4-dim gather + (4->64 proj) + bias + relu + LN ----------------
__global__ __launch_bounds__(128) void k_layer1(const float* __restrict__ W1,
                                                const float* __restrict__ b1,
                                                const float* __restrict__ lng,
                                                const float* __restrict__ lnb) {
    __shared__ float sW[4 * HID];
    int t = threadIdx.x;
    sW[t] = W1[t];
    sW[t + 128] = W1[t + 128];
    __syncthreads();
    int n = blockIdx.x * 128 + t;
    if (n >= NN) return;
    const float4* e4 = (const float4*)g_e4s;
    float4 agg = __ldg(&e4[n]);  // self term (extra dinv applied below)
    int beg = g_rowptr[n], end = g_rowptr[n + 1];
    int e = beg;
    for (; e + 4 <= end; e += 4) {
        float4 v0 = __ldg(&e4[__ldg(&g_col[e])]);
        float4 v1 = __ldg(&e4[__ldg(&g_col[e + 1])]);
        float4 v2 = __ldg(&e4[__ldg(&g_col[e + 2])]);
        float4 v3 = __ldg(&e4[__ldg(&g_col[e + 3])]);
        agg.x += (v0.x + v1.x) + (v2.x + v3.x);
        agg.y += (v0.y + v1.y) + (v2.y + v3.y);
        agg.z += (v0.z + v1.z) + (v2.z + v3.z);
        agg.w += (v0.w + v1.w) + (v2.w + v3.w);
    }
    for (; e < end; e++) {
        float4 v = __ldg(&e4[__ldg(&g_col[e])]);
        agg.x += v.x; agg.y += v.y; agg.z += v.z; agg.w += v.w;
    }
    float di = g_dinv[n];
    // careful: self term needs dinv^2 * e4raw = dinv * e4s -> already e4s; total = dinv*(sum_src e4s + e4s[n])? 
    // out = dinv[n]*(Sum e4s[src]) + dinv[n]^2*e4raw[n] = dinv[n]*(Sum e4s[src] + e4s[n])
    agg.x *= di; agg.y *= di; agg.z *= di; agg.w *= di;
    float v[HID];
    float mu = 0.f;
#pragma unroll
    for (int j = 0; j < HID; j++) {
        float r = fmaf(agg.x, sW[j], fmaf(agg.y, sW[64 + j],
                  fmaf(agg.z, sW[128 + j], fmaf(agg.w, sW[192 + j], __ldg(&b1[j])))));
        r = fmaxf(r, 0.f);
        v[j] = r;
        mu += r;
    }
    mu *= (1.f / 64.f);
    float var = 0.f;
#pragma unroll
    for (int j = 0; j < HID; j++) {
        float d = v[j] - mu;
        v[j] = d;
        var = fmaf(d, d, var);
    }
    float rs = rsqrtf(var * (1.f / 64.f) + 1e-5f);
    float4* o = (float4*)(g_bufA + (size_t)n * HID);
#pragma unroll
    for (int j4 = 0; j4 < 16; j4++) {
        float r[4];
#pragma unroll
        for (int u = 0; u < 4; u++) {
            int j = 4 * j4 + u;
            r[u] = fmaf(v[j] * rs, __ldg(&lng[j]), __ldg(&lnb[j]));
        }
        o[j4] = make_float4(r[0], r[1], r[2], r[3]);
    }
}

// ---------------- layers 2/3 dense: hs = (bufA @ W) * dinv ----------------
__global__ __launch_bounds__(128) void k_mm(const float* __restrict__ W) {
    __shared__ float sW[HID * HID];
    int t = threadIdx.x;
    for (int i = t; i < HID * HID; i += 128) sW[i] = W[i];
    __syncthreads();
    int n = blockIdx.x * 128 + t;
    if (n >= NN) return;
    float acc[HID];
#pragma unroll
    for (int j = 0; j < HID; j++) acc[j] = 0.f;
    const float4* x4 = (const float4*)(g_bufA + (size_t)n * HID);
    for (int k4 = 0; k4 < 16; k4++) {
        float4 xv = x4[k4];
        const float4* w0 = (const float4*)(sW + (4 * k4 + 0) * HID);
        const float4* w1 = (const float4*)(sW + (4 * k4 + 1) * HID);
        const float4* w2 = (const float4*)(sW + (4 * k4 + 2) * HID);
        const float4* w3 = (const float4*)(sW + (4 * k4 + 3) * HID);
#pragma unroll
        for (int j = 0; j < 16; j++) {
            float4 a = w0[j], b = w1[j], c = w2[j], d = w3[j];
            acc[4 * j + 0] = fmaf(xv.x, a.x, fmaf(xv.y, b.x, fmaf(xv.z, c.x, fmaf(xv.w, d.x, acc[4 * j + 0]))));
            acc[4 * j + 1] = fmaf(xv.x, a.y, fmaf(xv.y, b.y, fmaf(xv.z, c.y, fmaf(xv.w, d.y, acc[4 * j + 1]))));
            acc[4 * j + 2] = fmaf(xv.x, a.z, fmaf(xv.y, b.z, fmaf(xv.z, c.z, fmaf(xv.w, d.z, acc[4 * j + 2]))));
            acc[4 * j + 3] = fmaf(xv.x, a.w, fmaf(xv.y, b.w, fmaf(xv.z, c.w, fmaf(xv.w, d.w, acc[4 * j + 3]))));
        }
    }
    float di = g_dinv[n];
    float4* o = (float4*)(g_bufB + (size_t)n * HID);
#pragma unroll
    for (int j = 0; j < 16; j++)
        o[j] = make_float4(acc[4 * j] * di, acc[4 * j + 1] * di, acc[4 * j + 2] * di, acc[4 * j + 3] * di);
}

// ---------------- fused 64-dim gather + relu (+LN | +pool), warp per node ----------------
template <bool LN, bool POOL>
__global__ __launch_bounds__(256) void k_gather(const float* __restrict__ bias,
                                                const float* __restrict__ lng,
                                                const float* __restrict__ lnb,
                                                const int* __restrict__ batch) {
    int n = (blockIdx.x * blockDim.x + threadIdx.x) >> 5;
    int lane = threadIdx.x & 31;
    if (n >= NN) return;
    const float2* hs2 = (const float2*)g_bufB;
    float2 acc = __ldg(&hs2[(size_t)n * 32 + lane]);  // self-loop term (pre-scaled)
    int beg = g_rowptr[n], end = g_rowptr[n + 1];
    int e = beg;
    int m8 = beg + ((end - beg) & ~7);
    for (; e < m8; e += 8) {
        int s0 = __ldg(&g_col[e + 0]), s1 = __ldg(&g_col[e + 1]);
        int s2 = __ldg(&g_col[e + 2]), s3 = __ldg(&g_col[e + 3]);
        int s4 = __ldg(&g_col[e + 4]), s5 = __ldg(&g_col[e + 5]);
        int s6 = __ldg(&g_col[e + 6]), s7 = __ldg(&g_col[e + 7]);
        float2 v0 = __ldg(&hs2[(size_t)s0 * 32 + lane]);
        float2 v1 = __ldg(&hs2[(size_t)s1 * 32 + lane]);
        float2 v2 = __ldg(&hs2[(size_t)s2 * 32 + lane]);
        float2 v3 = __ldg(&hs2[(size_t)s3 * 32 + lane]);
        float2 v4 = __ldg(&hs2[(size_t)s4 * 32 + lane]);
        float2 v5 = __ldg(&hs2[(size_t)s5 * 32 + lane]);
        float2 v6 = __ldg(&hs2[(size_t)s6 * 32 + lane]);
        float2 v7 = __ldg(&hs2[(size_t)s7 * 32 + lane]);
        acc.x += ((v0.x + v1.x) + (v2.x + v3.x)) + ((v4.x + v5.x) + (v6.x + v7.x));
        acc.y += ((v0.y + v1.y) + (v2.y + v3.y)) + ((v4.y + v5.y) + (v6.y + v7.y));
    }
    for (; e < end; e++) {
        int s = __ldg(&g_col[e]);
        float2 v = __ldg(&hs2[(size_t)s * 32 + lane]);
        acc.x += v.x;
        acc.y += v.y;
    }
    float di = g_dinv[n];
    int f = lane * 2;
    float vx = fmaxf(fmaf(di, acc.x, __ldg(&bias[f])), 0.f);
    float vy = fmaxf(fmaf(di, acc.y, __ldg(&bias[f + 1])), 0.f);
    if (LN) {
        float s = vx + vy;
#pragma unroll
        for (int o = 16; o; o >>= 1) s += __shfl_xor_sync(0xffffffffu, s, o);
        float mu = s * (1.f / 64.f);
        float dx = vx - mu, dy = vy - mu;
        float q = dx * dx + dy * dy;
#pragma unroll
        for (int o = 16; o; o >>= 1) q += __shfl_xor_sync(0xffffffffu, q, o);
        float r = rsqrtf(q * (1.f / 64.f) + 1e-5f);
        vx = fmaf(dx * r, __ldg(&lng[f]), __ldg(&lnb[f]));
        vy = fmaf(dy * r, __ldg(&lng[f + 1]), __ldg(&lnb[f + 1]));
    }
    if (POOL) {
        int g = __ldg(&batch[n]);
        atomicAdd(&g_pool[g * HID + f], vx);
        atomicAdd(&g_pool[g * HID + f + 1], vy);
        if (lane == 0) atomicAdd(&g_cnt[g], 1);
    } else {
        ((float2*)g_bufA)[(size_t)n * 32 + lane] = make_float2(vx, vy);
    }
}

// ---------------- final MLP: out = (pool/cnt) @ pW1 + pb1, then @ pW2 + pb2 ----------------
__global__ __launch_bounds__(1024) void k_mlp(const float* __restrict__ pW1,
                                              const float* __restrict__ pb1,
                                              const float* __restrict__ pW2,
                                              const float* __restrict__ pb2,
                                              float* __restrict__ out) {
    __shared__ float sp[NG * HID];
    __shared__ float sh[NG * HID];
    int t = threadIdx.x;  // 1024
    for (int i = t; i < NG * HID; i += 1024) {
        int g = i >> 6;
        float c = (float)max(g_cnt[g], 1);
        sp[i] = g_pool[i] / c;
    }
    __syncthreads();
    for (int i = t; i < NG * HID; i += 1024) {
        int g = i >> 6, j = i & 63;
        float a = pb1[j];
        for (int k = 0; k < HID; k++) a = fmaf(sp[g * HID + k], pW1[k * HID + j], a);
        sh[i] = a;
    }
    __syncthreads();
    for (int i = t; i < NG * HID; i += 1024) {
        int g = i >> 6, j = i & 63;
        float a = pb2[j];
        for (int k = 0; k < HID; k++) a = fmaf(sh[g * HID + k], pW2[k * HID + j], a);
        out[i] = a;
    }
}

// ---------------- launcher ----------------
extern "C" void kernel_launch(void* const* d_in, const int* in_sizes, int n_in,
                              void* d_out, int out_size) {
    const int* node = (const int*)d_in[0];
    const int* src = (const int*)d_in[1];
    const int* dst = (const int*)d_in[2];
    const int* batch = (const int*)d_in[3];
    const float* emb = (const float*)d_in[4];
    const float* W1 = (const float*)d_in[5];
    const float* b1 = (const float*)d_in[6];
    const float* W2 = (const float*)d_in[7];
    const float* b2 = (const float*)d_in[8];
    const float* W3 = (const float*)d_in[9];
    const float* b3 = (const float*)d_in[10];
    const float* ln1g = (const float*)d_in[11];
    const float* ln1b = (const float*)d_in[12];
    const float* ln2g = (const float*)d_in[13];
    const float* ln2b = (const float*)d_in[14];
    const float* pW1 = (const float*)d_in[15];
    const float* pb1 = (const float*)d_in[16];
    const float* pW2 = (const float*)d_in[17];
    const float* pb2 = (const float*)d_in[18];
    float* out = (float*)d_out;

    const int TB = 256;
    k_zero<<<(NN + TB - 1) / TB, TB>>>();
    k_deg<<<(NE + TB - 1) / TB, TB>>>(dst);
    k_scanA<<<NB, 256>>>();
    k_scanB<<<1, 256>>>();
    k_scanC<<<NB, 256>>>(node, emb);
    k_fill<<<(NE + TB - 1) / TB, TB>>>(src, dst);

    dim3 gmm((NN + 127) / 128);
    dim3 ggt((NN * 32 + TB - 1) / TB);

    // layer 1 (fully fused)
    k_layer1<<<gmm, 128>>>(W1, b1, ln1g, ln1b);
    // layer 2
    k_mm<<<gmm, 128>>>(W2);
    k_gather<true, false><<<ggt, TB>>>(b2, ln2g, ln2b, nullptr);
    // layer 3 (+ fused mean-pool accumulate)
    k_mm<<<gmm, 128>>>(W3);
    k_gather<false, true><<<ggt, TB>>>(b3, nullptr, nullptr, batch);
    // MLP head
    k_mlp<<<1, 1024>>>(pW1, pb1, pW2, pb2, out);
}